// round 5
// baseline (speedup 1.0000x reference)
#include <cuda_runtime.h>

#define N_NODES_MAX 100000
#define IN_CH 256
#define QK_GRID 740            // 148 SMs * 5 blocks (regs=48 -> 5 resident)
#define POOL_GRID 888          // 148 SMs * 6 blocks
#define EMB_BLOCKS 32          // last 32 pool blocks do the final matvec

__device__ float g_q[N_NODES_MAX];
__device__ float g_k[N_NODES_MAX];
__device__ float g_aw[N_NODES_MAX];
__device__ float g_sum;
__device__ float g_s[IN_CH];
__device__ int   g_counter;
__device__ int   g_sink;

// ---------------------------------------------------------------------------
// Kernel 1: init scratch + q[n] = x[n]·Wq + bq, k[n] = x[n]·Wk + bk
// Warp per node, grid-stride, weights register-resident, 4x unroll.
// x read with __ldcs (evict-first) to keep L2 clean; edge indices prefetched
// into L2 so the edge kernel's index reads are L2 hits.
// ---------------------------------------------------------------------------
__global__ void __launch_bounds__(256, 5)
qk_kernel(const float* __restrict__ x,
          const float* __restrict__ Wq, const float* __restrict__ bq,
          const float* __restrict__ Wk, const float* __restrict__ bk,
          const int*   __restrict__ ei,     // edge_index, 2*n_edges ints
          float* __restrict__ out,          // zero out[0:256] for emb atomics
          int n_nodes, int n_edges) {
    int tid     = blockIdx.x * blockDim.x + threadIdx.x;
    int nthread = gridDim.x * blockDim.x;

    if (tid < n_nodes) g_aw[tid] = 0.0f;
    if (tid < IN_CH)  { g_s[tid] = 0.0f; out[tid] = 0.0f; }
    if (tid == 0)     { g_sum = 0.0f; g_counter = 0; }

    // ---- prefetch edge indices into L2 (node ids < 2^17, bit30 never set) ----
    {
        const int4* ei4 = reinterpret_cast<const int4*>(ei);
        int total4 = (2 * n_edges) >> 2;
        int acc = 0;
        for (int i = tid; i < total4; i += nthread) {
            int4 v = __ldcg(&ei4[i]);
            acc |= v.x | v.y | v.z | v.w;
        }
        if (acc & 0x40000000) g_sink = acc;   // never true — defeats DCE
    }

    int lane   = threadIdx.x & 31;
    int warp   = tid >> 5;
    int nwarps = nthread >> 5;

    const float4* wq4 = reinterpret_cast<const float4*>(Wq);
    const float4* wk4 = reinterpret_cast<const float4*>(Wk);
    float4 q0 = wq4[lane], q1 = wq4[lane + 32];
    float4 k0 = wk4[lane], k1 = wk4[lane + 32];
    float bqv = bq[0], bkv = bk[0];

    int n = warp;
    for (; n + 3 * nwarps < n_nodes; n += 4 * nwarps) {
        float dq[4], dk[4];
        #pragma unroll
        for (int u = 0; u < 4; u++) {
            const float4* xr = reinterpret_cast<const float4*>(
                x + (size_t)(n + u * nwarps) * IN_CH);
            float4 a = __ldcs(&xr[lane]);
            float4 b = __ldcs(&xr[lane + 32]);
            dq[u] = a.x*q0.x + a.y*q0.y + a.z*q0.z + a.w*q0.w
                  + b.x*q1.x + b.y*q1.y + b.z*q1.z + b.w*q1.w;
            dk[u] = a.x*k0.x + a.y*k0.y + a.z*k0.z + a.w*k0.w
                  + b.x*k1.x + b.y*k1.y + b.z*k1.z + b.w*k1.w;
        }
        #pragma unroll
        for (int o = 16; o > 0; o >>= 1) {
            #pragma unroll
            for (int u = 0; u < 4; u++) {
                dq[u] += __shfl_xor_sync(0xffffffffu, dq[u], o);
                dk[u] += __shfl_xor_sync(0xffffffffu, dk[u], o);
            }
        }
        if (lane == 0) {
            #pragma unroll
            for (int u = 0; u < 4; u++) {
                g_q[n + u * nwarps] = dq[u] + bqv;
                g_k[n + u * nwarps] = dk[u] + bkv;
            }
        }
    }
    for (; n < n_nodes; n += nwarps) {
        const float4* xr = reinterpret_cast<const float4*>(x + (size_t)n * IN_CH);
        float4 a = __ldcs(&xr[lane]);
        float4 b = __ldcs(&xr[lane + 32]);
        float dq = a.x*q0.x + a.y*q0.y + a.z*q0.z + a.w*q0.w
                 + b.x*q1.x + b.y*q1.y + b.z*q1.z + b.w*q1.w;
        float dk = a.x*k0.x + a.y*k0.y + a.z*k0.z + a.w*k0.w
                 + b.x*k1.x + b.y*k1.y + b.z*k1.z + b.w*k1.w;
        #pragma unroll
        for (int o = 16; o > 0; o >>= 1) {
            dq += __shfl_xor_sync(0xffffffffu, dq, o);
            dk += __shfl_xor_sync(0xffffffffu, dk, o);
        }
        if (lane == 0) { g_q[n] = dq + bqv; g_k[n] = dk + bkv; }
    }
}

// ---------------------------------------------------------------------------
// Kernel 2: edge pass, 8 edges/iter (indices L2-hot from qk prefetch).
// Also prefetches Wv+bv into L2 for the fused emb in pool.
// ---------------------------------------------------------------------------
__global__ void __launch_bounds__(256, 6)
edge_kernel(const int* __restrict__ row,
            const int* __restrict__ col,
            const float* __restrict__ Wv,
            const float* __restrict__ bv,
            int n_edges) {
    if (blockIdx.x < 64) {
        const float4* wv4 = reinterpret_cast<const float4*>(Wv);
        float4 p = __ldcg(&wv4[blockIdx.x * 256 + threadIdx.x]);
        float t = p.x + p.y + p.z + p.w;
        if (blockIdx.x == 0 && threadIdx.x < 64)
            t += __ldcg(&bv[threadIdx.x * 4]);
        if (t != t) atomicAdd(&g_sum, t);   // never true (no NaNs) — defeats DCE
    }

    int tid    = blockIdx.x * blockDim.x + threadIdx.x;
    int stride = gridDim.x * blockDim.x;
    int noct   = n_edges >> 3;

    const int4* row4 = reinterpret_cast<const int4*>(row);
    const int4* col4 = reinterpret_cast<const int4*>(col);

    float local = 0.0f;
    for (int i = tid; i < noct; i += stride) {
        int4 r0 = row4[2 * i], r1 = row4[2 * i + 1];
        int4 c0 = col4[2 * i], c1 = col4[2 * i + 1];

        float q0 = g_q[r0.x], q1 = g_q[r0.y], q2 = g_q[r0.z], q3 = g_q[r0.w];
        float q4 = g_q[r1.x], q5 = g_q[r1.y], q6 = g_q[r1.z], q7 = g_q[r1.w];
        float k0 = g_k[c0.x], k1 = g_k[c0.y], k2 = g_k[c0.z], k3 = g_k[c0.w];
        float k4 = g_k[c1.x], k5 = g_k[c1.y], k6 = g_k[c1.z], k7 = g_k[c1.w];

        float a0 = q0*k0, a1 = q1*k1, a2 = q2*k2, a3 = q3*k3;
        float a4 = q4*k4, a5 = q5*k5, a6 = q6*k6, a7 = q7*k7;
        a0 = (a0 > 0.f) ? a0 : 0.2f*a0;  a1 = (a1 > 0.f) ? a1 : 0.2f*a1;
        a2 = (a2 > 0.f) ? a2 : 0.2f*a2;  a3 = (a3 > 0.f) ? a3 : 0.2f*a3;
        a4 = (a4 > 0.f) ? a4 : 0.2f*a4;  a5 = (a5 > 0.f) ? a5 : 0.2f*a5;
        a6 = (a6 > 0.f) ? a6 : 0.2f*a6;  a7 = (a7 > 0.f) ? a7 : 0.2f*a7;
        float e0 = __expf(a0), e1 = __expf(a1), e2 = __expf(a2), e3 = __expf(a3);
        float e4 = __expf(a4), e5 = __expf(a5), e6 = __expf(a6), e7 = __expf(a7);

        atomicAdd(&g_aw[r0.x], e0);
        atomicAdd(&g_aw[r0.y], e1);
        atomicAdd(&g_aw[r0.z], e2);
        atomicAdd(&g_aw[r0.w], e3);
        atomicAdd(&g_aw[r1.x], e4);
        atomicAdd(&g_aw[r1.y], e5);
        atomicAdd(&g_aw[r1.z], e6);
        atomicAdd(&g_aw[r1.w], e7);
        local += ((e0 + e1) + (e2 + e3)) + ((e4 + e5) + (e6 + e7));
    }
    for (int e = (noct << 3) + tid; e < n_edges; e += stride) {
        float a = g_q[row[e]] * g_k[col[e]];
        a = (a > 0.f) ? a : 0.2f * a;
        float ex = __expf(a);
        atomicAdd(&g_aw[row[e]], ex);
        local += ex;
    }

    __shared__ float sh[32];
    #pragma unroll
    for (int o = 16; o > 0; o >>= 1) local += __shfl_xor_sync(0xffffffffu, local, o);
    if ((threadIdx.x & 31) == 0) sh[threadIdx.x >> 5] = local;
    __syncthreads();
    if (threadIdx.x < 32) {
        float v = (threadIdx.x < (blockDim.x >> 5)) ? sh[threadIdx.x] : 0.0f;
        #pragma unroll
        for (int o = 16; o > 0; o >>= 1) v += __shfl_xor_sync(0xffffffffu, v, o);
        if (threadIdx.x == 0) atomicAdd(&g_sum, v);
    }
}

// ---------------------------------------------------------------------------
// Kernel 3: normalize aw + s = sum_n aw_norm[n] * x[n], FUSED final matvec.
// x via __ldcs (streaming). Last EMB_BLOCKS blocks compute s·Wv + bv.
// ---------------------------------------------------------------------------
__global__ void __launch_bounds__(256, 6)
pool_kernel(const float* __restrict__ x,
            const float* __restrict__ Wv,
            const float* __restrict__ bv,
            float* __restrict__ graph_emb,
            float* __restrict__ aw_out,
            int n_nodes) {
    float inv = 1.0f / g_sum;
    int tid     = blockIdx.x * blockDim.x + threadIdx.x;
    int c4      = tid & 63;
    int n0      = tid >> 6;
    int nstride = (gridDim.x * blockDim.x) >> 6;

    float accx = 0.f, accy = 0.f, accz = 0.f, accw = 0.f;

    int n = n0;
    for (; n + 3 * nstride < n_nodes; n += 4 * nstride) {
        int na = n, nb = n + nstride, nc = n + 2 * nstride, nd = n + 3 * nstride;
        float w0 = g_aw[na] * inv;
        float w1 = g_aw[nb] * inv;
        float w2 = g_aw[nc] * inv;
        float w3 = g_aw[nd] * inv;
        float4 a0 = __ldcs(&reinterpret_cast<const float4*>(x + (size_t)na * IN_CH)[c4]);
        float4 a1 = __ldcs(&reinterpret_cast<const float4*>(x + (size_t)nb * IN_CH)[c4]);
        float4 a2 = __ldcs(&reinterpret_cast<const float4*>(x + (size_t)nc * IN_CH)[c4]);
        float4 a3 = __ldcs(&reinterpret_cast<const float4*>(x + (size_t)nd * IN_CH)[c4]);
        if (c4 == 0) {
            aw_out[na] = w0; aw_out[nb] = w1; aw_out[nc] = w2; aw_out[nd] = w3;
        }
        accx += w0*a0.x + w1*a1.x + w2*a2.x + w3*a3.x;
        accy += w0*a0.y + w1*a1.y + w2*a2.y + w3*a3.y;
        accz += w0*a0.z + w1*a1.z + w2*a2.z + w3*a3.z;
        accw += w0*a0.w + w1*a1.w + w2*a2.w + w3*a3.w;
    }
    for (; n < n_nodes; n += nstride) {
        float w = g_aw[n] * inv;
        float4 a = __ldcs(&reinterpret_cast<const float4*>(x + (size_t)n * IN_CH)[c4]);
        if (c4 == 0) aw_out[n] = w;
        accx += w*a.x; accy += w*a.y; accz += w*a.z; accw += w*a.w;
    }

    __shared__ float s_sh[IN_CH];
    if (threadIdx.x < IN_CH) s_sh[threadIdx.x] = 0.0f;
    __syncthreads();
    int cbase = c4 * 4;
    atomicAdd(&s_sh[cbase + 0], accx);
    atomicAdd(&s_sh[cbase + 1], accy);
    atomicAdd(&s_sh[cbase + 2], accz);
    atomicAdd(&s_sh[cbase + 3], accw);
    __syncthreads();
    if (threadIdx.x < IN_CH) atomicAdd(&g_s[threadIdx.x], s_sh[threadIdx.x]);

    // ---- fused emb: ticketed last-32-blocks pattern ----
    __threadfence();
    __shared__ int ticket_s;
    if (threadIdx.x == 0) ticket_s = atomicAdd(&g_counter, 1);
    __syncthreads();
    int ticket = ticket_s;
    int nb_tot = gridDim.x;

    if (ticket >= nb_tot - EMB_BLOCKS) {
        if (threadIdx.x == 0) {
            while (*((volatile int*)&g_counter) < nb_tot) { }
        }
        __syncthreads();
        __threadfence();

        int role = ticket - (nb_tot - EMB_BLOCKS);     // 0..31
        int c    = threadIdx.x;                        // 0..255
        int i0   = role * (IN_CH / EMB_BLOCKS);        // 8 i-rows per block
        float acc = 0.0f;
        #pragma unroll
        for (int u = 0; u < IN_CH / EMB_BLOCKS; u++)
            acc += __ldcg(&g_s[i0 + u]) * __ldg(&Wv[(size_t)(i0 + u) * IN_CH + c]);
        if (role == 0) acc += bv[c];
        atomicAdd(&graph_emb[c], acc);
    }
}

// ---------------------------------------------------------------------------
extern "C" void kernel_launch(void* const* d_in, const int* in_sizes, int n_in,
                              void* d_out, int out_size) {
    const float* x   = (const float*)d_in[0];
    const int*   ei  = (const int*)  d_in[1];
    const float* Wq  = (const float*)d_in[2];
    const float* bq  = (const float*)d_in[3];
    const float* Wk  = (const float*)d_in[4];
    const float* bk  = (const float*)d_in[5];
    const float* Wv  = (const float*)d_in[6];
    const float* bv  = (const float*)d_in[7];

    int n_nodes = in_sizes[0] / IN_CH;
    int n_edges = in_sizes[1] / 2;

    float* out = (float*)d_out;
    float* graph_emb = out;          // [256]
    float* aw_out    = out + IN_CH;  // [n_nodes]

    const int* row = ei;
    const int* col = ei + n_edges;

    qk_kernel<<<QK_GRID, 256>>>(x, Wq, bq, Wk, bk, ei, graph_emb, n_nodes, n_edges);
    edge_kernel<<<POOL_GRID, 256>>>(row, col, Wv, bv, n_edges);
    pool_kernel<<<POOL_GRID, 256>>>(x, Wv, bv, graph_emb, aw_out, n_nodes);
}

// round 6
// speedup vs baseline: 1.0198x; 1.0198x over previous
#include <cuda_runtime.h>

#define N_NODES_MAX 100000
#define IN_CH 256
#define GRID6 888              // 148 SMs * 6 blocks
#define EMB_BLOCKS 32          // last 32 pool blocks do the final matvec

__device__ float g_q[N_NODES_MAX];
__device__ float g_k[N_NODES_MAX];
__device__ float g_aw[N_NODES_MAX];
__device__ float g_sum;
__device__ float g_s[IN_CH];
__device__ int   g_counter;

// ---------------------------------------------------------------------------
// Kernel 1: init scratch + q[n] = x[n]·Wq + bq, k[n] = x[n]·Wk + bk
// Warp per node, grid-stride, weights register-resident, 4x unroll.
// launch_bounds(256,6): force <=41 regs so 6 blocks/SM fit -> 75% occ ceiling.
// ---------------------------------------------------------------------------
__global__ void __launch_bounds__(256, 6)
qk_kernel(const float* __restrict__ x,
          const float* __restrict__ Wq, const float* __restrict__ bq,
          const float* __restrict__ Wk, const float* __restrict__ bk,
          float* __restrict__ out,          // zero out[0:256] for emb atomics
          int n_nodes) {
    int tid     = blockIdx.x * blockDim.x + threadIdx.x;
    int nthread = gridDim.x * blockDim.x;

    if (tid < n_nodes) g_aw[tid] = 0.0f;
    if (tid < IN_CH)  { g_s[tid] = 0.0f; out[tid] = 0.0f; }
    if (tid == 0)     { g_sum = 0.0f; g_counter = 0; }

    int lane   = threadIdx.x & 31;
    int warp   = tid >> 5;
    int nwarps = nthread >> 5;

    const float4* wq4 = reinterpret_cast<const float4*>(Wq);
    const float4* wk4 = reinterpret_cast<const float4*>(Wk);
    float4 q0 = wq4[lane], q1 = wq4[lane + 32];
    float4 k0 = wk4[lane], k1 = wk4[lane + 32];
    float bqv = bq[0], bkv = bk[0];

    int n = warp;
    for (; n + 3 * nwarps < n_nodes; n += 4 * nwarps) {
        float dq[4], dk[4];
        #pragma unroll
        for (int u = 0; u < 4; u++) {
            const float4* xr = reinterpret_cast<const float4*>(
                x + (size_t)(n + u * nwarps) * IN_CH);
            float4 a = __ldcs(&xr[lane]);
            float4 b = __ldcs(&xr[lane + 32]);
            dq[u] = a.x*q0.x + a.y*q0.y + a.z*q0.z + a.w*q0.w
                  + b.x*q1.x + b.y*q1.y + b.z*q1.z + b.w*q1.w;
            dk[u] = a.x*k0.x + a.y*k0.y + a.z*k0.z + a.w*k0.w
                  + b.x*k1.x + b.y*k1.y + b.z*k1.z + b.w*k1.w;
        }
        #pragma unroll
        for (int o = 16; o > 0; o >>= 1) {
            #pragma unroll
            for (int u = 0; u < 4; u++) {
                dq[u] += __shfl_xor_sync(0xffffffffu, dq[u], o);
                dk[u] += __shfl_xor_sync(0xffffffffu, dk[u], o);
            }
        }
        if (lane == 0) {
            #pragma unroll
            for (int u = 0; u < 4; u++) {
                g_q[n + u * nwarps] = dq[u] + bqv;
                g_k[n + u * nwarps] = dk[u] + bkv;
            }
        }
    }
    for (; n < n_nodes; n += nwarps) {
        const float4* xr = reinterpret_cast<const float4*>(x + (size_t)n * IN_CH);
        float4 a = __ldcs(&xr[lane]);
        float4 b = __ldcs(&xr[lane + 32]);
        float dq = a.x*q0.x + a.y*q0.y + a.z*q0.z + a.w*q0.w
                 + b.x*q1.x + b.y*q1.y + b.z*q1.z + b.w*q1.w;
        float dk = a.x*k0.x + a.y*k0.y + a.z*k0.z + a.w*k0.w
                 + b.x*k1.x + b.y*k1.y + b.z*k1.z + b.w*k1.w;
        #pragma unroll
        for (int o = 16; o > 0; o >>= 1) {
            dq += __shfl_xor_sync(0xffffffffu, dq, o);
            dk += __shfl_xor_sync(0xffffffffu, dk, o);
        }
        if (lane == 0) { g_q[n] = dq + bqv; g_k[n] = dk + bkv; }
    }
}

// ---------------------------------------------------------------------------
// Kernel 2: edge pass, 8 edges/iter. Prefetches Wv+bv into L2 for fused emb.
// ---------------------------------------------------------------------------
__global__ void __launch_bounds__(256, 6)
edge_kernel(const int* __restrict__ row,
            const int* __restrict__ col,
            const float* __restrict__ Wv,
            const float* __restrict__ bv,
            int n_edges) {
    if (blockIdx.x < 64) {
        const float4* wv4 = reinterpret_cast<const float4*>(Wv);
        float4 p = __ldcg(&wv4[blockIdx.x * 256 + threadIdx.x]);
        float t = p.x + p.y + p.z + p.w;
        if (blockIdx.x == 0 && threadIdx.x < 64)
            t += __ldcg(&bv[threadIdx.x * 4]);
        if (t != t) atomicAdd(&g_sum, t);   // never true (no NaNs) — defeats DCE
    }

    int tid    = blockIdx.x * blockDim.x + threadIdx.x;
    int stride = gridDim.x * blockDim.x;
    int noct   = n_edges >> 3;

    const int4* row4 = reinterpret_cast<const int4*>(row);
    const int4* col4 = reinterpret_cast<const int4*>(col);

    float local = 0.0f;
    for (int i = tid; i < noct; i += stride) {
        int4 r0 = row4[2 * i], r1 = row4[2 * i + 1];
        int4 c0 = col4[2 * i], c1 = col4[2 * i + 1];

        float q0 = g_q[r0.x], q1 = g_q[r0.y], q2 = g_q[r0.z], q3 = g_q[r0.w];
        float q4 = g_q[r1.x], q5 = g_q[r1.y], q6 = g_q[r1.z], q7 = g_q[r1.w];
        float k0 = g_k[c0.x], k1 = g_k[c0.y], k2 = g_k[c0.z], k3 = g_k[c0.w];
        float k4 = g_k[c1.x], k5 = g_k[c1.y], k6 = g_k[c1.z], k7 = g_k[c1.w];

        float a0 = q0*k0, a1 = q1*k1, a2 = q2*k2, a3 = q3*k3;
        float a4 = q4*k4, a5 = q5*k5, a6 = q6*k6, a7 = q7*k7;
        a0 = (a0 > 0.f) ? a0 : 0.2f*a0;  a1 = (a1 > 0.f) ? a1 : 0.2f*a1;
        a2 = (a2 > 0.f) ? a2 : 0.2f*a2;  a3 = (a3 > 0.f) ? a3 : 0.2f*a3;
        a4 = (a4 > 0.f) ? a4 : 0.2f*a4;  a5 = (a5 > 0.f) ? a5 : 0.2f*a5;
        a6 = (a6 > 0.f) ? a6 : 0.2f*a6;  a7 = (a7 > 0.f) ? a7 : 0.2f*a7;
        float e0 = __expf(a0), e1 = __expf(a1), e2 = __expf(a2), e3 = __expf(a3);
        float e4 = __expf(a4), e5 = __expf(a5), e6 = __expf(a6), e7 = __expf(a7);

        atomicAdd(&g_aw[r0.x], e0);
        atomicAdd(&g_aw[r0.y], e1);
        atomicAdd(&g_aw[r0.z], e2);
        atomicAdd(&g_aw[r0.w], e3);
        atomicAdd(&g_aw[r1.x], e4);
        atomicAdd(&g_aw[r1.y], e5);
        atomicAdd(&g_aw[r1.z], e6);
        atomicAdd(&g_aw[r1.w], e7);
        local += ((e0 + e1) + (e2 + e3)) + ((e4 + e5) + (e6 + e7));
    }
    for (int e = (noct << 3) + tid; e < n_edges; e += stride) {
        float a = g_q[row[e]] * g_k[col[e]];
        a = (a > 0.f) ? a : 0.2f * a;
        float ex = __expf(a);
        atomicAdd(&g_aw[row[e]], ex);
        local += ex;
    }

    __shared__ float sh[32];
    #pragma unroll
    for (int o = 16; o > 0; o >>= 1) local += __shfl_xor_sync(0xffffffffu, local, o);
    if ((threadIdx.x & 31) == 0) sh[threadIdx.x >> 5] = local;
    __syncthreads();
    if (threadIdx.x < 32) {
        float v = (threadIdx.x < (blockDim.x >> 5)) ? sh[threadIdx.x] : 0.0f;
        #pragma unroll
        for (int o = 16; o > 0; o >>= 1) v += __shfl_xor_sync(0xffffffffu, v, o);
        if (threadIdx.x == 0) atomicAdd(&g_sum, v);
    }
}

// ---------------------------------------------------------------------------
// Kernel 3: normalize aw + s = sum_n aw_norm[n] * x[n], FUSED final matvec.
// ---------------------------------------------------------------------------
__global__ void __launch_bounds__(256, 6)
pool_kernel(const float* __restrict__ x,
            const float* __restrict__ Wv,
            const float* __restrict__ bv,
            float* __restrict__ graph_emb,
            float* __restrict__ aw_out,
            int n_nodes) {
    float inv = 1.0f / g_sum;
    int tid     = blockIdx.x * blockDim.x + threadIdx.x;
    int c4      = tid & 63;
    int n0      = tid >> 6;
    int nstride = (gridDim.x * blockDim.x) >> 6;

    float accx = 0.f, accy = 0.f, accz = 0.f, accw = 0.f;

    int n = n0;
    for (; n + 3 * nstride < n_nodes; n += 4 * nstride) {
        int na = n, nb = n + nstride, nc = n + 2 * nstride, nd = n + 3 * nstride;
        float w0 = g_aw[na] * inv;
        float w1 = g_aw[nb] * inv;
        float w2 = g_aw[nc] * inv;
        float w3 = g_aw[nd] * inv;
        float4 a0 = __ldcs(&reinterpret_cast<const float4*>(x + (size_t)na * IN_CH)[c4]);
        float4 a1 = __ldcs(&reinterpret_cast<const float4*>(x + (size_t)nb * IN_CH)[c4]);
        float4 a2 = __ldcs(&reinterpret_cast<const float4*>(x + (size_t)nc * IN_CH)[c4]);
        float4 a3 = __ldcs(&reinterpret_cast<const float4*>(x + (size_t)nd * IN_CH)[c4]);
        if (c4 == 0) {
            aw_out[na] = w0; aw_out[nb] = w1; aw_out[nc] = w2; aw_out[nd] = w3;
        }
        accx += w0*a0.x + w1*a1.x + w2*a2.x + w3*a3.x;
        accy += w0*a0.y + w1*a1.y + w2*a2.y + w3*a3.y;
        accz += w0*a0.z + w1*a1.z + w2*a2.z + w3*a3.z;
        accw += w0*a0.w + w1*a1.w + w2*a2.w + w3*a3.w;
    }
    for (; n < n_nodes; n += nstride) {
        float w = g_aw[n] * inv;
        float4 a = __ldcs(&reinterpret_cast<const float4*>(x + (size_t)n * IN_CH)[c4]);
        if (c4 == 0) aw_out[n] = w;
        accx += w*a.x; accy += w*a.y; accz += w*a.z; accw += w*a.w;
    }

    __shared__ float s_sh[IN_CH];
    if (threadIdx.x < IN_CH) s_sh[threadIdx.x] = 0.0f;
    __syncthreads();
    int cbase = c4 * 4;
    atomicAdd(&s_sh[cbase + 0], accx);
    atomicAdd(&s_sh[cbase + 1], accy);
    atomicAdd(&s_sh[cbase + 2], accz);
    atomicAdd(&s_sh[cbase + 3], accw);
    __syncthreads();
    if (threadIdx.x < IN_CH) atomicAdd(&g_s[threadIdx.x], s_sh[threadIdx.x]);

    // ---- fused emb: ticketed last-32-blocks pattern ----
    __threadfence();
    __shared__ int ticket_s;
    if (threadIdx.x == 0) ticket_s = atomicAdd(&g_counter, 1);
    __syncthreads();
    int ticket = ticket_s;
    int nb_tot = gridDim.x;

    if (ticket >= nb_tot - EMB_BLOCKS) {
        if (threadIdx.x == 0) {
            while (*((volatile int*)&g_counter) < nb_tot) { }
        }
        __syncthreads();
        __threadfence();

        int role = ticket - (nb_tot - EMB_BLOCKS);     // 0..31
        int c    = threadIdx.x;                        // 0..255
        int i0   = role * (IN_CH / EMB_BLOCKS);        // 8 i-rows per block
        float acc = 0.0f;
        #pragma unroll
        for (int u = 0; u < IN_CH / EMB_BLOCKS; u++)
            acc += __ldcg(&g_s[i0 + u]) * __ldg(&Wv[(size_t)(i0 + u) * IN_CH + c]);
        if (role == 0) acc += bv[c];
        atomicAdd(&graph_emb[c], acc);
    }
}

// ---------------------------------------------------------------------------
extern "C" void kernel_launch(void* const* d_in, const int* in_sizes, int n_in,
                              void* d_out, int out_size) {
    const float* x   = (const float*)d_in[0];
    const int*   ei  = (const int*)  d_in[1];
    const float* Wq  = (const float*)d_in[2];
    const float* bq  = (const float*)d_in[3];
    const float* Wk  = (const float*)d_in[4];
    const float* bk  = (const float*)d_in[5];
    const float* Wv  = (const float*)d_in[6];
    const float* bv  = (const float*)d_in[7];

    int n_nodes = in_sizes[0] / IN_CH;
    int n_edges = in_sizes[1] / 2;

    float* out = (float*)d_out;
    float* graph_emb = out;          // [256]
    float* aw_out    = out + IN_CH;  // [n_nodes]

    const int* row = ei;
    const int* col = ei + n_edges;

    qk_kernel<<<GRID6, 256>>>(x, Wq, bq, Wk, bk, graph_emb, n_nodes);
    edge_kernel<<<GRID6, 256>>>(row, col, Wv, bv, n_edges);
    pool_kernel<<<GRID6, 256>>>(x, Wv, bv, graph_emb, aw_out, n_nodes);
}

// round 7
// speedup vs baseline: 1.1024x; 1.0810x over previous
#include <cuda_runtime.h>

#define N_NODES_MAX 100000
#define IN_CH 256
#define QK_GRID 740            // 148 SMs * 5 blocks (regs ~48)
#define GRID6 888              // 148 SMs * 6 blocks
#define EMB_BLOCKS 32          // last 32 pool blocks do the final matvec

__device__ float g_q[N_NODES_MAX];
__device__ float g_k[N_NODES_MAX];
__device__ float g_aw[N_NODES_MAX];
__device__ float g_sum;
__device__ float g_s[IN_CH];
__device__ int   g_counter;

// ---------------------------------------------------------------------------
// Kernel 1: init scratch + q[n] = x[n]·Wq + bq, k[n] = x[n]·Wk + bk
// Plain cached loads: x (102 MB) is deliberately left resident in L2 (126 MB)
// so pool_kernel's second read of x hits L2 instead of DRAM.
// ---------------------------------------------------------------------------
__global__ void __launch_bounds__(256)
qk_kernel(const float* __restrict__ x,
          const float* __restrict__ Wq, const float* __restrict__ bq,
          const float* __restrict__ Wk, const float* __restrict__ bk,
          float* __restrict__ out,          // zero out[0:256] for emb atomics
          int n_nodes) {
    int tid     = blockIdx.x * blockDim.x + threadIdx.x;
    int nthread = gridDim.x * blockDim.x;

    if (tid < n_nodes) g_aw[tid] = 0.0f;
    if (tid < IN_CH)  { g_s[tid] = 0.0f; out[tid] = 0.0f; }
    if (tid == 0)     { g_sum = 0.0f; g_counter = 0; }

    int lane   = threadIdx.x & 31;
    int warp   = tid >> 5;
    int nwarps = nthread >> 5;

    const float4* wq4 = reinterpret_cast<const float4*>(Wq);
    const float4* wk4 = reinterpret_cast<const float4*>(Wk);
    float4 q0 = wq4[lane], q1 = wq4[lane + 32];
    float4 k0 = wk4[lane], k1 = wk4[lane + 32];
    float bqv = bq[0], bkv = bk[0];

    int n = warp;
    for (; n + 3 * nwarps < n_nodes; n += 4 * nwarps) {
        float dq[4], dk[4];
        #pragma unroll
        for (int u = 0; u < 4; u++) {
            const float4* xr = reinterpret_cast<const float4*>(
                x + (size_t)(n + u * nwarps) * IN_CH);
            float4 a = xr[lane];
            float4 b = xr[lane + 32];
            dq[u] = a.x*q0.x + a.y*q0.y + a.z*q0.z + a.w*q0.w
                  + b.x*q1.x + b.y*q1.y + b.z*q1.z + b.w*q1.w;
            dk[u] = a.x*k0.x + a.y*k0.y + a.z*k0.z + a.w*k0.w
                  + b.x*k1.x + b.y*k1.y + b.z*k1.z + b.w*k1.w;
        }
        #pragma unroll
        for (int o = 16; o > 0; o >>= 1) {
            #pragma unroll
            for (int u = 0; u < 4; u++) {
                dq[u] += __shfl_xor_sync(0xffffffffu, dq[u], o);
                dk[u] += __shfl_xor_sync(0xffffffffu, dk[u], o);
            }
        }
        if (lane == 0) {
            #pragma unroll
            for (int u = 0; u < 4; u++) {
                g_q[n + u * nwarps] = dq[u] + bqv;
                g_k[n + u * nwarps] = dk[u] + bkv;
            }
        }
    }
    for (; n < n_nodes; n += nwarps) {
        const float4* xr = reinterpret_cast<const float4*>(x + (size_t)n * IN_CH);
        float4 a = xr[lane];
        float4 b = xr[lane + 32];
        float dq = a.x*q0.x + a.y*q0.y + a.z*q0.z + a.w*q0.w
                 + b.x*q1.x + b.y*q1.y + b.z*q1.z + b.w*q1.w;
        float dk = a.x*k0.x + a.y*k0.y + a.z*k0.z + a.w*k0.w
                 + b.x*k1.x + b.y*k1.y + b.z*k1.z + b.w*k1.w;
        #pragma unroll
        for (int o = 16; o > 0; o >>= 1) {
            dq += __shfl_xor_sync(0xffffffffu, dq, o);
            dk += __shfl_xor_sync(0xffffffffu, dk, o);
        }
        if (lane == 0) { g_q[n] = dq + bqv; g_k[n] = dk + bkv; }
    }
}

// ---------------------------------------------------------------------------
// Kernel 2: edge pass, 8 edges/iter. Index loads use __ldcs (evict-first) so
// the 25.6 MB index stream does NOT evict x from L2. Prefetches Wv+bv.
// ---------------------------------------------------------------------------
__global__ void __launch_bounds__(256, 6)
edge_kernel(const int* __restrict__ row,
            const int* __restrict__ col,
            const float* __restrict__ Wv,
            const float* __restrict__ bv,
            int n_edges) {
    if (blockIdx.x < 64) {
        const float4* wv4 = reinterpret_cast<const float4*>(Wv);
        float4 p = __ldcg(&wv4[blockIdx.x * 256 + threadIdx.x]);
        float t = p.x + p.y + p.z + p.w;
        if (blockIdx.x == 0 && threadIdx.x < 64)
            t += __ldcg(&bv[threadIdx.x * 4]);
        if (t != t) atomicAdd(&g_sum, t);   // never true (no NaNs) — defeats DCE
    }

    int tid    = blockIdx.x * blockDim.x + threadIdx.x;
    int stride = gridDim.x * blockDim.x;
    int noct   = n_edges >> 3;

    const int4* row4 = reinterpret_cast<const int4*>(row);
    const int4* col4 = reinterpret_cast<const int4*>(col);

    float local = 0.0f;
    for (int i = tid; i < noct; i += stride) {
        int4 r0 = __ldcs(&row4[2 * i]), r1 = __ldcs(&row4[2 * i + 1]);
        int4 c0 = __ldcs(&col4[2 * i]), c1 = __ldcs(&col4[2 * i + 1]);

        float q0 = g_q[r0.x], q1 = g_q[r0.y], q2 = g_q[r0.z], q3 = g_q[r0.w];
        float q4 = g_q[r1.x], q5 = g_q[r1.y], q6 = g_q[r1.z], q7 = g_q[r1.w];
        float k0 = g_k[c0.x], k1 = g_k[c0.y], k2 = g_k[c0.z], k3 = g_k[c0.w];
        float k4 = g_k[c1.x], k5 = g_k[c1.y], k6 = g_k[c1.z], k7 = g_k[c1.w];

        float a0 = q0*k0, a1 = q1*k1, a2 = q2*k2, a3 = q3*k3;
        float a4 = q4*k4, a5 = q5*k5, a6 = q6*k6, a7 = q7*k7;
        a0 = (a0 > 0.f) ? a0 : 0.2f*a0;  a1 = (a1 > 0.f) ? a1 : 0.2f*a1;
        a2 = (a2 > 0.f) ? a2 : 0.2f*a2;  a3 = (a3 > 0.f) ? a3 : 0.2f*a3;
        a4 = (a4 > 0.f) ? a4 : 0.2f*a4;  a5 = (a5 > 0.f) ? a5 : 0.2f*a5;
        a6 = (a6 > 0.f) ? a6 : 0.2f*a6;  a7 = (a7 > 0.f) ? a7 : 0.2f*a7;
        float e0 = __expf(a0), e1 = __expf(a1), e2 = __expf(a2), e3 = __expf(a3);
        float e4 = __expf(a4), e5 = __expf(a5), e6 = __expf(a6), e7 = __expf(a7);

        atomicAdd(&g_aw[r0.x], e0);
        atomicAdd(&g_aw[r0.y], e1);
        atomicAdd(&g_aw[r0.z], e2);
        atomicAdd(&g_aw[r0.w], e3);
        atomicAdd(&g_aw[r1.x], e4);
        atomicAdd(&g_aw[r1.y], e5);
        atomicAdd(&g_aw[r1.z], e6);
        atomicAdd(&g_aw[r1.w], e7);
        local += ((e0 + e1) + (e2 + e3)) + ((e4 + e5) + (e6 + e7));
    }
    for (int e = (noct << 3) + tid; e < n_edges; e += stride) {
        float a = g_q[row[e]] * g_k[col[e]];
        a = (a > 0.f) ? a : 0.2f * a;
        float ex = __expf(a);
        atomicAdd(&g_aw[row[e]], ex);
        local += ex;
    }

    __shared__ float sh[32];
    #pragma unroll
    for (int o = 16; o > 0; o >>= 1) local += __shfl_xor_sync(0xffffffffu, local, o);
    if ((threadIdx.x & 31) == 0) sh[threadIdx.x >> 5] = local;
    __syncthreads();
    if (threadIdx.x < 32) {
        float v = (threadIdx.x < (blockDim.x >> 5)) ? sh[threadIdx.x] : 0.0f;
        #pragma unroll
        for (int o = 16; o > 0; o >>= 1) v += __shfl_xor_sync(0xffffffffu, v, o);
        if (threadIdx.x == 0) atomicAdd(&g_sum, v);
    }
}

// ---------------------------------------------------------------------------
// Kernel 3: normalize aw + s = sum_n aw_norm[n] * x[n], FUSED final matvec.
// x reads via __ldcg: mostly L2 hits (x left resident by qk_kernel).
// ---------------------------------------------------------------------------
__global__ void __launch_bounds__(256, 6)
pool_kernel(const float* __restrict__ x,
            const float* __restrict__ Wv,
            const float* __restrict__ bv,
            float* __restrict__ graph_emb,
            float* __restrict__ aw_out,
            int n_nodes) {
    float inv = 1.0f / g_sum;
    int tid     = blockIdx.x * blockDim.x + threadIdx.x;
    int c4      = tid & 63;
    int n0      = tid >> 6;
    int nstride = (gridDim.x * blockDim.x) >> 6;

    float accx = 0.f, accy = 0.f, accz = 0.f, accw = 0.f;

    int n = n0;
    for (; n + 3 * nstride < n_nodes; n += 4 * nstride) {
        int na = n, nb = n + nstride, nc = n + 2 * nstride, nd = n + 3 * nstride;
        float w0 = g_aw[na] * inv;
        float w1 = g_aw[nb] * inv;
        float w2 = g_aw[nc] * inv;
        float w3 = g_aw[nd] * inv;
        float4 a0 = __ldcg(&reinterpret_cast<const float4*>(x + (size_t)na * IN_CH)[c4]);
        float4 a1 = __ldcg(&reinterpret_cast<const float4*>(x + (size_t)nb * IN_CH)[c4]);
        float4 a2 = __ldcg(&reinterpret_cast<const float4*>(x + (size_t)nc * IN_CH)[c4]);
        float4 a3 = __ldcg(&reinterpret_cast<const float4*>(x + (size_t)nd * IN_CH)[c4]);
        if (c4 == 0) {
            aw_out[na] = w0; aw_out[nb] = w1; aw_out[nc] = w2; aw_out[nd] = w3;
        }
        accx += w0*a0.x + w1*a1.x + w2*a2.x + w3*a3.x;
        accy += w0*a0.y + w1*a1.y + w2*a2.y + w3*a3.y;
        accz += w0*a0.z + w1*a1.z + w2*a2.z + w3*a3.z;
        accw += w0*a0.w + w1*a1.w + w2*a2.w + w3*a3.w;
    }
    for (; n < n_nodes; n += nstride) {
        float w = g_aw[n] * inv;
        float4 a = __ldcg(&reinterpret_cast<const float4*>(x + (size_t)n * IN_CH)[c4]);
        if (c4 == 0) aw_out[n] = w;
        accx += w*a.x; accy += w*a.y; accz += w*a.z; accw += w*a.w;
    }

    __shared__ float s_sh[IN_CH];
    if (threadIdx.x < IN_CH) s_sh[threadIdx.x] = 0.0f;
    __syncthreads();
    int cbase = c4 * 4;
    atomicAdd(&s_sh[cbase + 0], accx);
    atomicAdd(&s_sh[cbase + 1], accy);
    atomicAdd(&s_sh[cbase + 2], accz);
    atomicAdd(&s_sh[cbase + 3], accw);
    __syncthreads();
    if (threadIdx.x < IN_CH) atomicAdd(&g_s[threadIdx.x], s_sh[threadIdx.x]);

    // ---- fused emb: ticketed last-32-blocks pattern ----
    __threadfence();
    __shared__ int ticket_s;
    if (threadIdx.x == 0) ticket_s = atomicAdd(&g_counter, 1);
    __syncthreads();
    int ticket = ticket_s;
    int nb_tot = gridDim.x;

    if (ticket >= nb_tot - EMB_BLOCKS) {
        if (threadIdx.x == 0) {
            while (*((volatile int*)&g_counter) < nb_tot) { }
        }
        __syncthreads();
        __threadfence();

        int role = ticket - (nb_tot - EMB_BLOCKS);     // 0..31
        int c    = threadIdx.x;                        // 0..255
        int i0   = role * (IN_CH / EMB_BLOCKS);        // 8 i-rows per block
        float acc = 0.0f;
        #pragma unroll
        for (int u = 0; u < IN_CH / EMB_BLOCKS; u++)
            acc += __ldcg(&g_s[i0 + u]) * __ldg(&Wv[(size_t)(i0 + u) * IN_CH + c]);
        if (role == 0) acc += bv[c];
        atomicAdd(&graph_emb[c], acc);
    }
}

// ---------------------------------------------------------------------------
extern "C" void kernel_launch(void* const* d_in, const int* in_sizes, int n_in,
                              void* d_out, int out_size) {
    const float* x   = (const float*)d_in[0];
    const int*   ei  = (const int*)  d_in[1];
    const float* Wq  = (const float*)d_in[2];
    const float* bq  = (const float*)d_in[3];
    const float* Wk  = (const float*)d_in[4];
    const float* bk  = (const float*)d_in[5];
    const float* Wv  = (const float*)d_in[6];
    const float* bv  = (const float*)d_in[7];

    int n_nodes = in_sizes[0] / IN_CH;
    int n_edges = in_sizes[1] / 2;

    float* out = (float*)d_out;
    float* graph_emb = out;          // [256]
    float* aw_out    = out + IN_CH;  // [n_nodes]

    const int* row = ei;
    const int* col = ei + n_edges;

    qk_kernel<<<QK_GRID, 256>>>(x, Wq, bq, Wk, bk, graph_emb, n_nodes);
    edge_kernel<<<GRID6, 256>>>(row, col, Wv, bv, n_edges);
    pool_kernel<<<GRID6, 256>>>(x, Wv, bv, graph_emb, aw_out, n_nodes);
}

// round 8
// speedup vs baseline: 1.1203x; 1.0162x over previous
#include <cuda_runtime.h>

#define N_NODES_MAX 100000
#define IN_CH 256
#define QK_GRID 740            // 148 SMs * 5 blocks (regs ~48)
#define GRID6 888              // 148 SMs * 6 blocks
#define EMB_BLOCKS 32          // last 32 pool blocks do the final matvec
#define LOG2E 1.4426950408889634f

__device__ float g_q[N_NODES_MAX];
__device__ float g_k[N_NODES_MAX];   // stores k * log2(e)
__device__ float g_aw[N_NODES_MAX];
__device__ float g_sum;
__device__ float g_s[IN_CH];
__device__ int   g_counter;

// ---------------------------------------------------------------------------
// Kernel 1: init scratch + q[n] = x[n]·Wq + bq, k[n] = (x[n]·Wk + bk)·log2e.
// Plain cached loads: x (102 MB) deliberately left resident in L2 (126 MB)
// so pool_kernel's second read of x hits L2 instead of DRAM.
// ---------------------------------------------------------------------------
__global__ void __launch_bounds__(256)
qk_kernel(const float* __restrict__ x,
          const float* __restrict__ Wq, const float* __restrict__ bq,
          const float* __restrict__ Wk, const float* __restrict__ bk,
          float* __restrict__ out,          // zero out[0:256] for emb atomics
          int n_nodes) {
    int tid     = blockIdx.x * blockDim.x + threadIdx.x;
    int nthread = gridDim.x * blockDim.x;

    if (tid < n_nodes) g_aw[tid] = 0.0f;
    if (tid < IN_CH)  { g_s[tid] = 0.0f; out[tid] = 0.0f; }
    if (tid == 0)     { g_sum = 0.0f; g_counter = 0; }

    int lane   = threadIdx.x & 31;
    int warp   = tid >> 5;
    int nwarps = nthread >> 5;

    const float4* wq4 = reinterpret_cast<const float4*>(Wq);
    const float4* wk4 = reinterpret_cast<const float4*>(Wk);
    float4 q0 = wq4[lane], q1 = wq4[lane + 32];
    float4 k0 = wk4[lane], k1 = wk4[lane + 32];
    float bqv = bq[0], bkv = bk[0];

    int n = warp;
    for (; n + 3 * nwarps < n_nodes; n += 4 * nwarps) {
        float dq[4], dk[4];
        #pragma unroll
        for (int u = 0; u < 4; u++) {
            const float4* xr = reinterpret_cast<const float4*>(
                x + (size_t)(n + u * nwarps) * IN_CH);
            float4 a = xr[lane];
            float4 b = xr[lane + 32];
            dq[u] = a.x*q0.x + a.y*q0.y + a.z*q0.z + a.w*q0.w
                  + b.x*q1.x + b.y*q1.y + b.z*q1.z + b.w*q1.w;
            dk[u] = a.x*k0.x + a.y*k0.y + a.z*k0.z + a.w*k0.w
                  + b.x*k1.x + b.y*k1.y + b.z*k1.z + b.w*k1.w;
        }
        #pragma unroll
        for (int o = 16; o > 0; o >>= 1) {
            #pragma unroll
            for (int u = 0; u < 4; u++) {
                dq[u] += __shfl_xor_sync(0xffffffffu, dq[u], o);
                dk[u] += __shfl_xor_sync(0xffffffffu, dk[u], o);
            }
        }
        if (lane == 0) {
            #pragma unroll
            for (int u = 0; u < 4; u++) {
                g_q[n + u * nwarps] = dq[u] + bqv;
                g_k[n + u * nwarps] = (dk[u] + bkv) * LOG2E;
            }
        }
    }
    for (; n < n_nodes; n += nwarps) {
        const float4* xr = reinterpret_cast<const float4*>(x + (size_t)n * IN_CH);
        float4 a = xr[lane];
        float4 b = xr[lane + 32];
        float dq = a.x*q0.x + a.y*q0.y + a.z*q0.z + a.w*q0.w
                 + b.x*q1.x + b.y*q1.y + b.z*q1.z + b.w*q1.w;
        float dk = a.x*k0.x + a.y*k0.y + a.z*k0.z + a.w*k0.w
                 + b.x*k1.x + b.y*k1.y + b.z*k1.z + b.w*k1.w;
        #pragma unroll
        for (int o = 16; o > 0; o >>= 1) {
            dq += __shfl_xor_sync(0xffffffffu, dq, o);
            dk += __shfl_xor_sync(0xffffffffu, dk, o);
        }
        if (lane == 0) { g_q[n] = dq + bqv; g_k[n] = (dk + bkv) * LOG2E; }
    }
}

// ---------------------------------------------------------------------------
// Kernel 2: edge pass, 8 edges/iter, issue-trimmed:
//   a = q[r] * k'[c]            (k' pre-scaled by log2e)
//   a = fmaxf(a, 0.2a)          (leaky, positively homogeneous)
//   e = exp2f(a)                (single MUFU.EX2, no extra FMUL)
// Index loads __ldcs (don't evict x from L2). Prefetches Wv+bv.
// ---------------------------------------------------------------------------
__global__ void __launch_bounds__(256, 6)
edge_kernel(const int* __restrict__ row,
            const int* __restrict__ col,
            const float* __restrict__ Wv,
            const float* __restrict__ bv,
            int n_edges) {
    if (blockIdx.x < 64) {
        const float4* wv4 = reinterpret_cast<const float4*>(Wv);
        float4 p = __ldcg(&wv4[blockIdx.x * 256 + threadIdx.x]);
        float t = p.x + p.y + p.z + p.w;
        if (blockIdx.x == 0 && threadIdx.x < 64)
            t += __ldcg(&bv[threadIdx.x * 4]);
        if (t != t) atomicAdd(&g_sum, t);   // never true (no NaNs) — defeats DCE
    }

    int tid    = blockIdx.x * blockDim.x + threadIdx.x;
    int stride = gridDim.x * blockDim.x;
    int noct   = n_edges >> 3;

    const int4* row4 = reinterpret_cast<const int4*>(row);
    const int4* col4 = reinterpret_cast<const int4*>(col);

    float local = 0.0f;
    for (int i = tid; i < noct; i += stride) {
        int4 r0 = __ldcs(&row4[2 * i]), r1 = __ldcs(&row4[2 * i + 1]);
        int4 c0 = __ldcs(&col4[2 * i]), c1 = __ldcs(&col4[2 * i + 1]);

        float q0 = g_q[r0.x], q1 = g_q[r0.y], q2 = g_q[r0.z], q3 = g_q[r0.w];
        float q4 = g_q[r1.x], q5 = g_q[r1.y], q6 = g_q[r1.z], q7 = g_q[r1.w];
        float k0 = g_k[c0.x], k1 = g_k[c0.y], k2 = g_k[c0.z], k3 = g_k[c0.w];
        float k4 = g_k[c1.x], k5 = g_k[c1.y], k6 = g_k[c1.z], k7 = g_k[c1.w];

        float a0 = q0*k0, a1 = q1*k1, a2 = q2*k2, a3 = q3*k3;
        float a4 = q4*k4, a5 = q5*k5, a6 = q6*k6, a7 = q7*k7;
        a0 = fmaxf(a0, 0.2f*a0);  a1 = fmaxf(a1, 0.2f*a1);
        a2 = fmaxf(a2, 0.2f*a2);  a3 = fmaxf(a3, 0.2f*a3);
        a4 = fmaxf(a4, 0.2f*a4);  a5 = fmaxf(a5, 0.2f*a5);
        a6 = fmaxf(a6, 0.2f*a6);  a7 = fmaxf(a7, 0.2f*a7);
        float e0 = exp2f(a0), e1 = exp2f(a1), e2 = exp2f(a2), e3 = exp2f(a3);
        float e4 = exp2f(a4), e5 = exp2f(a5), e6 = exp2f(a6), e7 = exp2f(a7);

        atomicAdd(&g_aw[r0.x], e0);
        atomicAdd(&g_aw[r0.y], e1);
        atomicAdd(&g_aw[r0.z], e2);
        atomicAdd(&g_aw[r0.w], e3);
        atomicAdd(&g_aw[r1.x], e4);
        atomicAdd(&g_aw[r1.y], e5);
        atomicAdd(&g_aw[r1.z], e6);
        atomicAdd(&g_aw[r1.w], e7);
        local += ((e0 + e1) + (e2 + e3)) + ((e4 + e5) + (e6 + e7));
    }
    for (int e = (noct << 3) + tid; e < n_edges; e += stride) {
        float a = g_q[row[e]] * g_k[col[e]];
        a = fmaxf(a, 0.2f * a);
        float ex = exp2f(a);
        atomicAdd(&g_aw[row[e]], ex);
        local += ex;
    }

    __shared__ float sh[32];
    #pragma unroll
    for (int o = 16; o > 0; o >>= 1) local += __shfl_xor_sync(0xffffffffu, local, o);
    if ((threadIdx.x & 31) == 0) sh[threadIdx.x >> 5] = local;
    __syncthreads();
    if (threadIdx.x < 32) {
        float v = (threadIdx.x < (blockDim.x >> 5)) ? sh[threadIdx.x] : 0.0f;
        #pragma unroll
        for (int o = 16; o > 0; o >>= 1) v += __shfl_xor_sync(0xffffffffu, v, o);
        if (threadIdx.x == 0) atomicAdd(&g_sum, v);
    }
}

// ---------------------------------------------------------------------------
// Kernel 3: normalize aw + s = sum_n aw_norm[n] * x[n], FUSED final matvec.
// x reads via __ldcg: mostly L2 hits (x left resident by qk_kernel).
// ---------------------------------------------------------------------------
__global__ void __launch_bounds__(256, 6)
pool_kernel(const float* __restrict__ x,
            const float* __restrict__ Wv,
            const float* __restrict__ bv,
            float* __restrict__ graph_emb,
            float* __restrict__ aw_out,
            int n_nodes) {
    float inv = 1.0f / g_sum;
    int tid     = blockIdx.x * blockDim.x + threadIdx.x;
    int c4      = tid & 63;
    int n0      = tid >> 6;
    int nstride = (gridDim.x * blockDim.x) >> 6;

    float accx = 0.f, accy = 0.f, accz = 0.f, accw = 0.f;

    int n = n0;
    for (; n + 3 * nstride < n_nodes; n += 4 * nstride) {
        int na = n, nb = n + nstride, nc = n + 2 * nstride, nd = n + 3 * nstride;
        float w0 = g_aw[na] * inv;
        float w1 = g_aw[nb] * inv;
        float w2 = g_aw[nc] * inv;
        float w3 = g_aw[nd] * inv;
        float4 a0 = __ldcg(&reinterpret_cast<const float4*>(x + (size_t)na * IN_CH)[c4]);
        float4 a1 = __ldcg(&reinterpret_cast<const float4*>(x + (size_t)nb * IN_CH)[c4]);
        float4 a2 = __ldcg(&reinterpret_cast<const float4*>(x + (size_t)nc * IN_CH)[c4]);
        float4 a3 = __ldcg(&reinterpret_cast<const float4*>(x + (size_t)nd * IN_CH)[c4]);
        if (c4 == 0) {
            aw_out[na] = w0; aw_out[nb] = w1; aw_out[nc] = w2; aw_out[nd] = w3;
        }
        accx += w0*a0.x + w1*a1.x + w2*a2.x + w3*a3.x;
        accy += w0*a0.y + w1*a1.y + w2*a2.y + w3*a3.y;
        accz += w0*a0.z + w1*a1.z + w2*a2.z + w3*a3.z;
        accw += w0*a0.w + w1*a1.w + w2*a2.w + w3*a3.w;
    }
    for (; n < n_nodes; n += nstride) {
        float w = g_aw[n] * inv;
        float4 a = __ldcg(&reinterpret_cast<const float4*>(x + (size_t)n * IN_CH)[c4]);
        if (c4 == 0) aw_out[n] = w;
        accx += w*a.x; accy += w*a.y; accz += w*a.z; accw += w*a.w;
    }

    __shared__ float s_sh[IN_CH];
    if (threadIdx.x < IN_CH) s_sh[threadIdx.x] = 0.0f;
    __syncthreads();
    int cbase = c4 * 4;
    atomicAdd(&s_sh[cbase + 0], accx);
    atomicAdd(&s_sh[cbase + 1], accy);
    atomicAdd(&s_sh[cbase + 2], accz);
    atomicAdd(&s_sh[cbase + 3], accw);
    __syncthreads();
    if (threadIdx.x < IN_CH) atomicAdd(&g_s[threadIdx.x], s_sh[threadIdx.x]);

    // ---- fused emb: ticketed last-32-blocks pattern ----
    __threadfence();
    __shared__ int ticket_s;
    if (threadIdx.x == 0) ticket_s = atomicAdd(&g_counter, 1);
    __syncthreads();
    int ticket = ticket_s;
    int nb_tot = gridDim.x;

    if (ticket >= nb_tot - EMB_BLOCKS) {
        if (threadIdx.x == 0) {
            while (*((volatile int*)&g_counter) < nb_tot) { }
        }
        __syncthreads();
        __threadfence();

        int role = ticket - (nb_tot - EMB_BLOCKS);     // 0..31
        int c    = threadIdx.x;                        // 0..255
        int i0   = role * (IN_CH / EMB_BLOCKS);        // 8 i-rows per block
        float acc = 0.0f;
        #pragma unroll
        for (int u = 0; u < IN_CH / EMB_BLOCKS; u++)
            acc += __ldcg(&g_s[i0 + u]) * __ldg(&Wv[(size_t)(i0 + u) * IN_CH + c]);
        if (role == 0) acc += bv[c];
        atomicAdd(&graph_emb[c], acc);
    }
}

// ---------------------------------------------------------------------------
extern "C" void kernel_launch(void* const* d_in, const int* in_sizes, int n_in,
                              void* d_out, int out_size) {
    const float* x   = (const float*)d_in[0];
    const int*   ei  = (const int*)  d_in[1];
    const float* Wq  = (const float*)d_in[2];
    const float* bq  = (const float*)d_in[3];
    const float* Wk  = (const float*)d_in[4];
    const float* bk  = (const float*)d_in[5];
    const float* Wv  = (const float*)d_in[6];
    const float* bv  = (const float*)d_in[7];

    int n_nodes = in_sizes[0] / IN_CH;
    int n_edges = in_sizes[1] / 2;

    float* out = (float*)d_out;
    float* graph_emb = out;          // [256]
    float* aw_out    = out + IN_CH;  // [n_nodes]

    const int* row = ei;
    const int* col = ei + n_edges;

    qk_kernel<<<QK_GRID, 256>>>(x, Wq, bq, Wk, bk, graph_emb, n_nodes);
    edge_kernel<<<GRID6, 256>>>(row, col, Wv, bv, n_edges);
    pool_kernel<<<GRID6, 256>>>(x, Wv, bv, graph_emb, aw_out, n_nodes);
}